// round 7
// baseline (speedup 1.0000x reference)
#include <cuda_runtime.h>
#include <cuda_bf16.h>
#include <math.h>
#include <stdint.h>

// CustomLSTM: 2-layer LSTM, B=128, T=512, IN=64, H=1024, OUT=1
// Round 7: single continuous cp.async pipeline across all 512*49 chunks,
// split-phase grid barriers (arrive early / wait late, hidden behind MMA work),
// layer1 K reordered (h1_prev before h0_new). mma.sync bf16 3-term split.

#define Bb    128
#define Tt    512
#define INP   64
#define Hh    1024
#define NBLK  128
#define NTHR  256

typedef unsigned int u32;
typedef unsigned short us;
typedef unsigned long long u64;

// ---- smem layout (us = 2-byte units) ----
#define ACT_PL   9216u                     // 128*72 us
#define W_PL     2304u                     // 32*72 us
#define STG_US   (2*ACT_PL + 2*W_PL)       // 23040 us / stage
#define NSTG     4
#define SGATE_US (NSTG * STG_US)           // 92160: float gate buffer [32][132]
#define HSTG_US  (SGATE_US + 8448u)        // 100608: h staging (2048 us)
#define DYN_SMEM ((HSTG_US + 2048u) * 2u)  // 205312 bytes

#define TOTAL_M  (Tt * 49)

// ---------------- device scratch ----------------
__device__ __align__(128) us d_h0[2][2][Bb][Hh];   // [buf][plane][b][k]
__device__ __align__(128) us d_h1[2][2][Bb][Hh];
__device__ __align__(128) us d_x[Tt][2][Bb][INP];
__device__ __align__(128) us d_w[128u * 49u * 2u * 32u * 64u];
__device__ float d_bias0[4096], d_bias1[4096];
__device__ float d_bi0[Bb * Hh], d_bi1[Bb * Hh];
__device__ float d_h1f[Bb * Hh];
__device__ u32 g_cntA, g_cntB;
__device__ volatile u32 g_genA, g_genB;
__device__ volatile u32 g_abort;

// ---------------- helpers ----------------
__device__ __forceinline__ u32 smem_u32(const void* p) {
    u32 a; asm("{ .reg .u64 t; cvta.to.shared.u64 t, %1; cvt.u32.u64 %0, t; }" : "=r"(a) : "l"(p));
    return a;
}
__device__ __forceinline__ void cpa16(u32 dst, const void* src) {
    asm volatile("cp.async.cg.shared.global [%0], [%1], 16;" :: "r"(dst), "l"(src));
}
#define CP_COMMIT() asm volatile("cp.async.commit_group;" ::: "memory")
#define CP_WAIT2()  asm volatile("cp.async.wait_group 2;" ::: "memory")

__device__ __forceinline__ void ldsm4(u32* r, u32 addr) {
    asm volatile("ldmatrix.sync.aligned.m8n8.x4.shared.b16 {%0,%1,%2,%3}, [%4];"
                 : "=r"(r[0]), "=r"(r[1]), "=r"(r[2]), "=r"(r[3]) : "r"(addr));
}
__device__ __forceinline__ void mma16816(float* c, const u32* a, u32 b0, u32 b1) {
    asm volatile("mma.sync.aligned.m16n8k16.row.col.f32.bf16.bf16.f32 "
                 "{%0,%1,%2,%3}, {%4,%5,%6,%7}, {%8,%9}, {%0,%1,%2,%3};"
                 : "+f"(c[0]), "+f"(c[1]), "+f"(c[2]), "+f"(c[3])
                 : "r"(a[0]), "r"(a[1]), "r"(a[2]), "r"(a[3]), "r"(b0), "r"(b1));
}

__device__ __forceinline__ float sigf(float x) { return __fdividef(1.f, 1.f + __expf(-x)); }
__device__ __forceinline__ float tanh_f(float x) {
    float xc = fminf(fmaxf(x, -15.f), 15.f);
    float e  = __expf(-2.f * xc);
    return (1.f - e) * __fdividef(1.f, 1.f + e);
}
__device__ __forceinline__ void bsplit(float v, us& hi, us& lo) {
    __nv_bfloat16 h = __float2bfloat16_rn(v);
    __nv_bfloat16 l = __float2bfloat16_rn(v - __bfloat162float(h));
    hi = __bfloat16_as_ushort(h); lo = __bfloat16_as_ushort(l);
}

// ---------------- split grid barrier ----------------
__device__ __forceinline__ void split_arrive(u32* cnt, volatile u32* gen, u32 target)
{
    __threadfence();
    __syncthreads();                 // all CTA writes globally visible
    if (threadIdx.x == 0) {
        u32 old = atomicAdd(cnt, 1u);
        if (old == NBLK - 1) {
            *cnt = 0;
            __threadfence();
            *gen = target;
        }
    }
}
__device__ __forceinline__ void split_wait(volatile u32* gen, u32 target)
{
    if (threadIdx.x == 0) {
        u32 i = 0;
        while (*gen < target) {
            __nanosleep(32);
            if (g_abort) break;
            if (++i > (1u << 24)) { g_abort = 1u; break; }
        }
    }
    __syncthreads();
}

// ---------------- setup kernels ----------------
__global__ void setup_misc(const float* __restrict__ boundary,
                           const float* __restrict__ bx0, const float* __restrict__ bh0,
                           const float* __restrict__ bb0, const float* __restrict__ Wb0,
                           const float* __restrict__ bx1, const float* __restrict__ bh1,
                           const float* __restrict__ bb1, const float* __restrict__ Wb1)
{
    int idx = blockIdx.x * 256 + threadIdx.x;   // 131072
    if (idx == 0) { g_cntA = 0; g_cntB = 0; g_genA = 0; g_genB = 0; g_abort = 0; }
    ((u32*)d_h0)[idx] = 0u;
    ((u32*)d_h1)[idx] = 0u;
    int b = idx >> 10, j = idx & 1023;
    float p0 = boundary[b * 2 + 0], p1 = boundary[b * 2 + 1];
    d_bi0[idx] = p0 * Wb0[j * 2 + 0] + p1 * Wb0[j * 2 + 1] + bb0[j];
    d_bi1[idx] = p0 * Wb1[j * 2 + 0] + p1 * Wb1[j * 2 + 1] + bb1[j];
    if (idx < 4096) {
        d_bias0[idx] = bx0[idx] + bh0[idx];
        d_bias1[idx] = bx1[idx] + bh1[idx];
    }
}

__global__ void setup_x(const float* __restrict__ x)
{
    int idx = blockIdx.x * 256 + threadIdx.x;   // 4194304
    int k = idx & 63, b = (idx >> 6) & 127, t = idx >> 13;
    float v = x[b * (Tt * INP) + t * INP + k];
    us hi, lo; bsplit(v, hi, lo);
    d_x[t][0][b][k] = hi;
    d_x[t][1][b][k] = lo;
}

__global__ void repack_w(const float* __restrict__ Uh0, const float* __restrict__ Wx0,
                         const float* __restrict__ Wx1, const float* __restrict__ Uh1)
{
    int idx = blockIdx.x * 256 + threadIdx.x;   // 12845056
    int k   = idx & 63;
    int r   = (idx >> 6) & 31;
    int w   = (idx >> 11) % 49;
    int cta = idx / (49 << 11);
    int g = r >> 3, u = r & 7;
    int grow = g * Hh + cta * 8 + u;
    float wv;
    if (w < 16)       wv = Uh0[grow * Hh + w * 64 + k];
    else if (w == 16) wv = Wx0[grow * INP + k];
    else if (w < 33)  wv = Wx1[grow * Hh + (w - 17) * 64 + k];
    else              wv = Uh1[grow * Hh + (w - 33) * 64 + k];
    us hi, lo; bsplit(wv, hi, lo);
    u64 base = ((u64)(cta * 49 + w)) * 2u * 2048u;
    d_w[base + 0    + r * 64 + k] = hi;
    d_w[base + 2048 + r * 64 + k] = lo;
}

// ---------------- stream chunk staging ----------------
// li: 0..15 h0_prev | 16 x_t | 17..32 h1_prev | 33..48 h0_new
__device__ __forceinline__ void load_stream(u32 Sa, int t, int li, int cta, int tid)
{
    const int rd = t & 1, wr = rd ^ 1;
    const us* aH; const us* aL; int K; int w;
    if (li < 16)      { w = li;      aH = &d_h0[rd][0][0][li * 64];        aL = &d_h0[rd][1][0][li * 64];        K = Hh; }
    else if (li == 16){ w = 16;      aH = &d_x[t][0][0][0];                aL = &d_x[t][1][0][0];                K = INP; }
    else if (li < 33) { w = li + 16; aH = &d_h1[rd][0][0][(li - 17) * 64]; aL = &d_h1[rd][1][0][(li - 17) * 64]; K = Hh; }
    else              { w = li - 16; aH = &d_h0[wr][0][0][(li - 33) * 64]; aL = &d_h0[wr][1][0][(li - 33) * 64]; K = Hh; }

#pragma unroll
    for (int i = 0; i < 4; ++i) {               // ActH
        int idx = tid + i * 256;
        int row = idx >> 3, seg = idx & 7;
        cpa16(Sa + (row * 72 + seg * 8) * 2, aH + row * K + seg * 8);
    }
#pragma unroll
    for (int i = 0; i < 4; ++i) {               // ActL
        int idx = tid + i * 256;
        int row = idx >> 3, seg = idx & 7;
        cpa16(Sa + (ACT_PL + row * 72 + seg * 8) * 2, aL + row * K + seg * 8);
    }
    const us* wsrc = d_w + ((u64)(cta * 49 + w)) * 2u * 2048u;
#pragma unroll
    for (int i = 0; i < 2; ++i) {               // W hi+lo
        int idx = tid + i * 256;
        int pl = idx >> 8, row = (idx >> 3) & 31, seg = idx & 7;
        cpa16(Sa + (2 * ACT_PL + pl * W_PL + row * 72 + seg * 8) * 2,
              wsrc + pl * 2048 + row * 64 + seg * 8);
    }
}

// ---------------- persistent LSTM kernel ----------------
__global__ void __launch_bounds__(NTHR, 1) lstm_mma()
{
    extern __shared__ __align__(16) us sm[];
    const int tid  = threadIdx.x;
    const int cta  = blockIdx.x;
    const int lane = tid & 31;
    const int wid  = tid >> 5;
    const int mrow = wid & 1;
    const int wcol = wid >> 1;
    const u32 smA  = smem_u32(sm);

    float* sgate = (float*)(sm + SGATE_US);
    us*    hstg  = sm + HSTG_US;

    const u32 aoff  = (u32)((mrow * 16 + (lane & 15)) * 72 + ((lane >> 4) * 8));
    const u32 boffA = (u32)((wcol * 32 + (lane & 7) + ((lane >> 4) & 1) * 8) * 72
                            + (((lane >> 3) & 1) * 8));
    const u32 boffB = boffA + 16 * 72;

    const int j = cta * 8 + wid;
    float bg0[4], bg1[4], bif0[4], bif1[4];
#pragma unroll
    for (int g = 0; g < 4; ++g) {
        bg0[g] = d_bias0[g * Hh + j];
        bg1[g] = d_bias1[g * Hh + j];
    }
#pragma unroll
    for (int p = 0; p < 4; ++p) {
        bif0[p] = d_bi0[(lane + 32 * p) * Hh + j];
        bif1[p] = d_bi1[(lane + 32 * p) * Hh + j];
    }
    float c0[4] = {0.f, 0.f, 0.f, 0.f};
    float c1[4] = {0.f, 0.f, 0.f, 0.f};

    float acc[4][4];
#pragma unroll
    for (int nt = 0; nt < 4; ++nt)
#pragma unroll
        for (int q = 0; q < 4; ++q) acc[nt][q] = 0.f;

    // prologue: 3 chunks in flight (t=0, li=0..2 — no gates needed)
    load_stream(smA + 0 * (STG_US * 2), 0, 0, cta, tid); CP_COMMIT();
    load_stream(smA + 1 * (STG_US * 2), 0, 1, cta, tid); CP_COMMIT();
    load_stream(smA + 2 * (STG_US * 2), 0, 2, cta, tid); CP_COMMIT();

    int t = 0, li = 0;
#pragma unroll 1
    for (u32 m = 0; m < (u32)TOTAL_M; ++m) {
        CP_WAIT2();                     // chunk m resident (always 1 commit/iter)
        __syncthreads();                // everyone done with stage (m-1)%4

        // ---- issue chunk m+3 into stage (m+3)&3 = (m-1)&3 ----
        {
            int li3 = li + 3, t3 = t;
            if (li3 >= 49) { li3 -= 49; ++t3; }
            if (t3 < Tt) {
                if (li3 == 17)      split_wait(&g_genB, (u32)t3);       // h1_prev ready
                else if (li3 == 33) split_wait(&g_genA, (u32)t3 + 1);   // h0_new ready
                load_stream(smA + (u32)((m + 3) & 3) * (STG_US * 2), t3, li3, cta, tid);
            }
            CP_COMMIT();                // commit EVERY iteration (maybe empty)
        }

        // ---- compute chunk m ----
        {
            const u32 SaB  = smA + (u32)(m & 3) * (STG_US * 2);
            const u32 actH = SaB;
            const u32 actL = SaB + ACT_PL * 2;
            const u32 whB  = SaB + (2 * ACT_PL) * 2;
            const u32 wlB  = SaB + (2 * ACT_PL + W_PL) * 2;
#pragma unroll
            for (int kk = 0; kk < 64; kk += 16) {
                const u32 k2 = (u32)kk * 2;
                u32 wh[4], wl[4], bh1[4], bh2[4], bl1[4], bl2[4];
                ldsm4(wh,  whB  + aoff * 2 + k2);
                ldsm4(wl,  wlB  + aoff * 2 + k2);
                ldsm4(bh1, actH + boffA * 2 + k2);
                ldsm4(bh2, actH + boffB * 2 + k2);
                ldsm4(bl1, actL + boffA * 2 + k2);
                ldsm4(bl2, actL + boffB * 2 + k2);

                mma16816(acc[0], wh, bh1[0], bh1[1]);
                mma16816(acc[1], wh, bh1[2], bh1[3]);
                mma16816(acc[2], wh, bh2[0], bh2[1]);
                mma16816(acc[3], wh, bh2[2], bh2[3]);
                mma16816(acc[0], wl, bh1[0], bh1[1]);
                mma16816(acc[1], wl, bh1[2], bh1[3]);
                mma16816(acc[2], wl, bh2[0], bh2[1]);
                mma16816(acc[3], wl, bh2[2], bh2[3]);
                mma16816(acc[0], wh, bl1[0], bl1[1]);
                mma16816(acc[1], wh, bl1[2], bl1[3]);
                mma16816(acc[2], wh, bl2[0], bl2[1]);
                mma16816(acc[3], wh, bl2[2], bl2[3]);
            }
        }

        // ---- layer epilogues ----
        if (li == 16 || li == 48) {
            const int layer = (li == 48);
            // acc -> sgate
            {
                const int row = mrow * 16 + (lane >> 2);
                const int col = wcol * 32 + (lane & 3) * 2;
#pragma unroll
                for (int nt = 0; nt < 4; ++nt) {
                    const int cb = col + nt * 8;
                    sgate[row * 132 + cb]           = acc[nt][0];
                    sgate[row * 132 + cb + 1]       = acc[nt][1];
                    sgate[(row + 8) * 132 + cb]     = acc[nt][2];
                    sgate[(row + 8) * 132 + cb + 1] = acc[nt][3];
                }
            }
            __syncthreads();
            // cell
            {
                const float* bg  = layer ? bg1 : bg0;
                const float* bif = layer ? bif1 : bif0;
                float* cc = layer ? c1 : c0;
#pragma unroll
                for (int p = 0; p < 4; ++p) {
                    const int b = lane + 32 * p;
                    float pi = sgate[(0  + wid) * 132 + b] + bg[0];
                    float pf = sgate[(8  + wid) * 132 + b] + bg[1] + bif[p];
                    float po = sgate[(16 + wid) * 132 + b] + bg[2];
                    float pg = sgate[(24 + wid) * 132 + b] + bg[3];
                    float iv = sigf(pi), fv = sigf(pf), ov = sigf(po), gg = tanh_f(pg);
                    float cn = fv * cc[p] + iv * gg;
                    cc[p] = cn;
                    float hv = ov * tanh_f(cn);
                    us hi, lo; bsplit(hv, hi, lo);
                    hstg[b * 8 + wid]        = hi;
                    hstg[1024 + b * 8 + wid] = lo;
                    if (layer == 1 && t == Tt - 1)
                        d_h1f[b * Hh + j] = hv;
                }
            }
            __syncthreads();
            // coalesced writeback
            {
                const int wr = (t & 1) ^ 1;
                const int pl = tid >> 7, b = tid & 127;
                uint4 v = *(const uint4*)(hstg + pl * 1024 + b * 8);
                us* dst = (layer ? &d_h1[wr][pl][b][cta * 8]
                                 : &d_h0[wr][pl][b][cta * 8]);
                *(uint4*)dst = v;
            }
            // early arrive (wait happens much later, hidden behind MMA work)
            if (!layer) split_arrive(&g_cntA, &g_genA, (u32)t + 1);
            else        split_arrive(&g_cntB, &g_genB, (u32)t + 1);

            // reset accumulators for next layer/step
#pragma unroll
            for (int nt = 0; nt < 4; ++nt)
#pragma unroll
                for (int q = 0; q < 4; ++q) acc[nt][q] = 0.f;

            if (layer && g_abort) break;
        }

        if (++li == 49) { li = 0; ++t; }
    }
}

// ---------------- fc head ----------------
__global__ void fc_kernel(const float* __restrict__ fcW,
                          const float* __restrict__ fcb,
                          float* __restrict__ out)
{
    __shared__ float red[256];
    int b = blockIdx.x, tid = threadIdx.x;
    float s = 0.f;
    for (int jj = tid; jj < Hh; jj += 256) s += d_h1f[b * Hh + jj] * fcW[jj];
    red[tid] = s;
    __syncthreads();
    for (int o = 128; o > 0; o >>= 1) {
        if (tid < o) red[tid] += red[tid + o];
        __syncthreads();
    }
    if (tid == 0) out[b] = red[0] + fcb[0];
}

// ---------------- launch (5 graph nodes) ----------------
extern "C" void kernel_launch(void* const* d_in, const int* in_sizes, int n_in,
                              void* d_out, int out_size)
{
    const float* x        = (const float*)d_in[0];
    const float* boundary = (const float*)d_in[1];
    const float* Wx0      = (const float*)d_in[2];
    const float* bx0      = (const float*)d_in[3];
    const float* Uh0      = (const float*)d_in[4];
    const float* bh0      = (const float*)d_in[5];
    const float* Wb0      = (const float*)d_in[6];
    const float* bb0      = (const float*)d_in[7];
    const float* Wx1      = (const float*)d_in[8];
    const float* bx1      = (const float*)d_in[9];
    const float* Uh1      = (const float*)d_in[10];
    const float* bh1      = (const float*)d_in[11];
    const float* Wb1      = (const float*)d_in[12];
    const float* bb1      = (const float*)d_in[13];
    const float* fcW      = (const float*)d_in[14];
    const float* fcb      = (const float*)d_in[15];
    float* out            = (float*)d_out;

    cudaFuncSetAttribute(lstm_mma, cudaFuncAttributeMaxDynamicSharedMemorySize, DYN_SMEM);

    setup_misc<<<(Bb * Hh) / 256, 256>>>(boundary, bx0, bh0, bb0, Wb0, bx1, bh1, bb1, Wb1);
    setup_x<<<(Tt * Bb * INP) / 256, 256>>>(x);
    repack_w<<<(128 * 49 * 32 * 64) / 256, 256>>>(Uh0, Wx0, Wx1, Uh1);
    lstm_mma<<<NBLK, NTHR, DYN_SMEM>>>();
    fc_kernel<<<Bb, 256>>>(fcW, fcb, out);
}

// round 8
// speedup vs baseline: 1.0704x; 1.0704x over previous
#include <cuda_runtime.h>
#include <cuda_bf16.h>
#include <math.h>
#include <stdint.h>

// CustomLSTM: 2-layer LSTM, B=128, T=512, IN=64, H=1024, OUT=1
// Round 8: R6 structure, but 512 threads / 16 warps per CTA (4 per SMSP) to
// hide ldmatrix/HMMA latency. Per-warp tile m16 x n16, 6 MMA + 4 ldsm per k16.

#define Bb    128
#define Tt    512
#define INP   64
#define Hh    1024
#define NBLK  128
#define NTHR  512

typedef unsigned int u32;
typedef unsigned short us;
typedef unsigned long long u64;

// ---- smem layout (us = 2-byte units) ----
#define ACT_PL   9216u              // 128*72 us
#define W_PL     2304u              // 32*72 us
#define STG_US   (2*ACT_PL + 2*W_PL)       // 23040 us / stage
#define NSTG     3
#define SGATE_US (NSTG * STG_US)           // float gate buffer [32][132]
#define HSTG_US  (SGATE_US + 8448u)        // h staging (2048 us)
#define DYN_SMEM ((HSTG_US + 2048u) * 2u)  // bytes = 159232

// ---------------- device scratch ----------------
__device__ __align__(128) us d_h0[2][2][Bb][Hh];   // [buf][plane][b][k]
__device__ __align__(128) us d_h1[2][2][Bb][Hh];
__device__ __align__(128) us d_x[Tt][2][Bb][INP];
__device__ __align__(128) us d_w[128u * 49u * 2u * 32u * 64u];
__device__ float d_bias0[4096], d_bias1[4096];
__device__ float d_bi0[Bb * Hh], d_bi1[Bb * Hh];
__device__ float d_h1f[Bb * Hh];
__device__ u32 g_count;
__device__ volatile u32 g_gen;
__device__ volatile u32 g_abort;

// ---------------- helpers ----------------
__device__ __forceinline__ u32 smem_u32(const void* p) {
    u32 a; asm("{ .reg .u64 t; cvta.to.shared.u64 t, %1; cvt.u32.u64 %0, t; }" : "=r"(a) : "l"(p));
    return a;
}
__device__ __forceinline__ void cpa16(u32 dst, const void* src) {
    asm volatile("cp.async.cg.shared.global [%0], [%1], 16;" :: "r"(dst), "l"(src));
}
#define CP_COMMIT() asm volatile("cp.async.commit_group;" ::: "memory")
#define CP_WAIT0()  asm volatile("cp.async.wait_group 0;" ::: "memory")
#define CP_WAIT1()  asm volatile("cp.async.wait_group 1;" ::: "memory")

__device__ __forceinline__ void ldsm4(u32* r, u32 addr) {
    asm volatile("ldmatrix.sync.aligned.m8n8.x4.shared.b16 {%0,%1,%2,%3}, [%4];"
                 : "=r"(r[0]), "=r"(r[1]), "=r"(r[2]), "=r"(r[3]) : "r"(addr));
}
__device__ __forceinline__ void mma16816(float* c, const u32* a, u32 b0, u32 b1) {
    asm volatile("mma.sync.aligned.m16n8k16.row.col.f32.bf16.bf16.f32 "
                 "{%0,%1,%2,%3}, {%4,%5,%6,%7}, {%8,%9}, {%0,%1,%2,%3};"
                 : "+f"(c[0]), "+f"(c[1]), "+f"(c[2]), "+f"(c[3])
                 : "r"(a[0]), "r"(a[1]), "r"(a[2]), "r"(a[3]), "r"(b0), "r"(b1));
}

__device__ __forceinline__ float sigf(float x) { return __fdividef(1.f, 1.f + __expf(-x)); }
__device__ __forceinline__ float tanh_f(float x) {
    float xc = fminf(fmaxf(x, -15.f), 15.f);
    float e  = __expf(-2.f * xc);
    return (1.f - e) * __fdividef(1.f, 1.f + e);
}
__device__ __forceinline__ void bsplit(float v, us& hi, us& lo) {
    __nv_bfloat16 h = __float2bfloat16_rn(v);
    __nv_bfloat16 l = __float2bfloat16_rn(v - __bfloat162float(h));
    hi = __bfloat16_as_ushort(h); lo = __bfloat16_as_ushort(l);
}

// ---------------- setup kernels ----------------
__global__ void setup_misc(const float* __restrict__ boundary,
                           const float* __restrict__ bx0, const float* __restrict__ bh0,
                           const float* __restrict__ bb0, const float* __restrict__ Wb0,
                           const float* __restrict__ bx1, const float* __restrict__ bh1,
                           const float* __restrict__ bb1, const float* __restrict__ Wb1)
{
    int idx = blockIdx.x * 256 + threadIdx.x;   // 131072
    if (idx == 0) { g_count = 0; g_gen = 0; g_abort = 0; }
    ((u32*)d_h0)[idx] = 0u;
    ((u32*)d_h1)[idx] = 0u;
    int b = idx >> 10, j = idx & 1023;
    float p0 = boundary[b * 2 + 0], p1 = boundary[b * 2 + 1];
    d_bi0[idx] = p0 * Wb0[j * 2 + 0] + p1 * Wb0[j * 2 + 1] + bb0[j];
    d_bi1[idx] = p0 * Wb1[j * 2 + 0] + p1 * Wb1[j * 2 + 1] + bb1[j];
    if (idx < 4096) {
        d_bias0[idx] = bx0[idx] + bh0[idx];
        d_bias1[idx] = bx1[idx] + bh1[idx];
    }
}

__global__ void setup_x(const float* __restrict__ x)
{
    int idx = blockIdx.x * 256 + threadIdx.x;   // 4194304
    int k = idx & 63, b = (idx >> 6) & 127, t = idx >> 13;
    float v = x[b * (Tt * INP) + t * INP + k];
    us hi, lo; bsplit(v, hi, lo);
    d_x[t][0][b][k] = hi;
    d_x[t][1][b][k] = lo;
}

__global__ void repack_w(const float* __restrict__ Uh0, const float* __restrict__ Wx0,
                         const float* __restrict__ Wx1, const float* __restrict__ Uh1)
{
    int idx = blockIdx.x * 256 + threadIdx.x;   // 12845056
    int k   = idx & 63;
    int r   = (idx >> 6) & 31;
    int w   = (idx >> 11) % 49;
    int cta = idx / (49 << 11);
    int g = r >> 3, u = r & 7;
    int grow = g * Hh + cta * 8 + u;
    float wv;
    if (w < 16)       wv = Uh0[grow * Hh + w * 64 + k];
    else if (w == 16) wv = Wx0[grow * INP + k];
    else if (w < 33)  wv = Wx1[grow * Hh + (w - 17) * 64 + k];
    else              wv = Uh1[grow * Hh + (w - 33) * 64 + k];
    us hi, lo; bsplit(wv, hi, lo);
    u64 base = ((u64)(cta * 49 + w)) * 2u * 2048u;
    d_w[base + 0    + r * 64 + k] = hi;
    d_w[base + 2048 + r * 64 + k] = lo;
}

// ---------------- grid barrier (bounded, abort-safe) ----------------
__device__ __forceinline__ void grid_barrier(u32 target)
{
    __threadfence();
    __syncthreads();
    if (threadIdx.x == 0) {
        u32 old = atomicAdd(&g_count, 1u);
        if (old == NBLK - 1) {
            g_count = 0;
            __threadfence();
            g_gen = target;
        } else {
            u32 i = 0;
            while (g_gen < target) {
                __nanosleep(64);
                if (g_abort) break;
                if (++i > (1u << 24)) { g_abort = 1u; break; }
            }
        }
    }
    __syncthreads();
}

// ---------------- chunk staging (512 threads: 5 x 16B each) ----------------
__device__ __forceinline__ void load_chunk(u32 Sa, int w, int t, int cta, int tid)
{
    int rd = t & 1, wr = rd ^ 1;
    const us* aH; const us* aL; int K;
    if (w < 16)      { aH = &d_h0[rd][0][0][w * 64];        aL = &d_h0[rd][1][0][w * 64];        K = Hh; }
    else if (w == 16){ aH = &d_x[t][0][0][0];               aL = &d_x[t][1][0][0];               K = INP; }
    else if (w < 33) { aH = &d_h0[wr][0][0][(w - 17) * 64]; aL = &d_h0[wr][1][0][(w - 17) * 64]; K = Hh; }
    else             { aH = &d_h1[rd][0][0][(w - 33) * 64]; aL = &d_h1[rd][1][0][(w - 33) * 64]; K = Hh; }

#pragma unroll
    for (int i = 0; i < 2; ++i) {               // ActH: 1024 x 16B
        int idx = tid + i * 512;
        int row = idx >> 3, seg = idx & 7;
        cpa16(Sa + (row * 72 + seg * 8) * 2, aH + row * K + seg * 8);
    }
#pragma unroll
    for (int i = 0; i < 2; ++i) {               // ActL
        int idx = tid + i * 512;
        int row = idx >> 3, seg = idx & 7;
        cpa16(Sa + (ACT_PL + row * 72 + seg * 8) * 2, aL + row * K + seg * 8);
    }
    const us* wsrc = d_w + ((u64)(cta * 49 + w)) * 2u * 2048u;
    {                                           // W hi+lo: 512 x 16B
        int pl = tid >> 8, row = (tid >> 3) & 31, seg = tid & 7;
        cpa16(Sa + (2 * ACT_PL + pl * W_PL + row * 72 + seg * 8) * 2,
              wsrc + pl * 2048 + row * 64 + seg * 8);
    }
}

// ---------------- persistent LSTM kernel ----------------
__global__ void __launch_bounds__(NTHR, 1) lstm_mma()
{
    extern __shared__ __align__(16) us sm[];
    const int tid  = threadIdx.x;
    const int cta  = blockIdx.x;
    const int lane = tid & 31;
    const int wid  = tid >> 5;          // 0..15
    const int mrow = wid & 1;           // M tile: gate rows 0-15 / 16-31
    const int ncol = wid >> 1;          // batch col group (x16)
    const u32 smA  = smem_u32(sm);

    float* sgate = (float*)(sm + SGATE_US);
    us*    hstg  = sm + HSTG_US;

    // ldmatrix per-lane source offsets (us units within a stage)
    const u32 aoff = (u32)((mrow * 16 + (lane & 15)) * 72 + ((lane >> 4) * 8));
    const u32 boff = (u32)((ncol * 16 + (lane & 7) + ((lane >> 4) & 1) * 8) * 72
                           + (((lane >> 3) & 1) * 8));

    // cell ownership: unit u = tid>>6 (0..7), batches b = (tid&63), +64
    const int cu = tid >> 6;
    const int cb = tid & 63;
    const int j  = cta * 8 + cu;
    float bg0[4], bg1[4], bif0[2], bif1[2];
#pragma unroll
    for (int g = 0; g < 4; ++g) {
        bg0[g] = d_bias0[g * Hh + j];
        bg1[g] = d_bias1[g * Hh + j];
    }
#pragma unroll
    for (int p = 0; p < 2; ++p) {
        bif0[p] = d_bi0[(cb + 64 * p) * Hh + j];
        bif1[p] = d_bi1[(cb + 64 * p) * Hh + j];
    }
    float c0[2] = {0.f, 0.f};
    float c1[2] = {0.f, 0.f};

    for (int t = 0; t < Tt && !g_abort; ++t) {
        const int wr = (t & 1) ^ 1;
#pragma unroll 1
        for (int layer = 0; layer < 2; ++layer) {
            const int wbeg = layer ? 17 : 0;
            const int nc   = layer ? 32 : 17;

            float acc[2][4];
#pragma unroll
            for (int nt = 0; nt < 2; ++nt)
#pragma unroll
                for (int q = 0; q < 4; ++q) acc[nt][q] = 0.f;

            // prologue: 2 chunks in flight
            load_chunk(smA, wbeg, t, cta, tid);
            CP_COMMIT();
            if (nc > 1) {
                load_chunk(smA + STG_US * 2, wbeg + 1, t, cta, tid);
                CP_COMMIT();
            }

#pragma unroll 1
            for (int ci = 0; ci < nc; ++ci) {
                if (ci + 1 < nc) CP_WAIT1(); else CP_WAIT0();
                __syncthreads();

                const u32 SaB  = smA + (u32)(ci % NSTG) * (STG_US * 2);
                const u32 actH = SaB;
                const u32 actL = SaB + ACT_PL * 2;
                const u32 whB  = SaB + (2 * ACT_PL) * 2;
                const u32 wlB  = SaB + (2 * ACT_PL + W_PL) * 2;
#pragma unroll
                for (int kk = 0; kk < 64; kk += 16) {
                    const u32 k2 = (u32)kk * 2;
                    u32 wh[4], wl[4], bh[4], bl[4];
                    ldsm4(wh, whB  + aoff * 2 + k2);
                    ldsm4(wl, wlB  + aoff * 2 + k2);
                    ldsm4(bh, actH + boff * 2 + k2);
                    ldsm4(bl, actL + boff * 2 + k2);

                    mma16816(acc[0], wh, bh[0], bh[1]);
                    mma16816(acc[1], wh, bh[2], bh[3]);
                    mma16816(acc[0], wl, bh[0], bh[1]);
                    mma16816(acc[1], wl, bh[2], bh[3]);
                    mma16816(acc[0], wh, bl[0], bl[1]);
                    mma16816(acc[1], wh, bl[2], bl[3]);
                }

                if (ci + 2 < nc) {
                    load_chunk(smA + (u32)((ci + 2) % NSTG) * (STG_US * 2),
                               wbeg + ci + 2, t, cta, tid);
                    CP_COMMIT();
                }
            }

            // ---- epilogue: acc -> sgate ----
            {
                const int row = mrow * 16 + (lane >> 2);
                const int col = ncol * 16 + (lane & 3) * 2;
#pragma unroll
                for (int nt = 0; nt < 2; ++nt) {
                    const int cbase = col + nt * 8;
                    sgate[row * 132 + cbase]           = acc[nt][0];
                    sgate[row * 132 + cbase + 1]       = acc[nt][1];
                    sgate[(row + 8) * 132 + cbase]     = acc[nt][2];
                    sgate[(row + 8) * 132 + cbase + 1] = acc[nt][3];
                }
            }
            __syncthreads();

            // ---- cell: unit cu, batches cb, cb+64 ----
            {
                const float* bg  = layer ? bg1 : bg0;
                const float* bif = layer ? bif1 : bif0;
                float* cc = layer ? c1 : c0;
#pragma unroll
                for (int p = 0; p < 2; ++p) {
                    const int b = cb + 64 * p;
                    float pi = sgate[(0  + cu) * 132 + b] + bg[0];
                    float pf = sgate[(8  + cu) * 132 + b] + bg[1] + bif[p];
                    float po = sgate[(16 + cu) * 132 + b] + bg[2];
                    float pg = sgate[(24 + cu) * 132 + b] + bg[3];
                    float iv = sigf(pi), fv = sigf(pf), ov = sigf(po), gg = tanh_f(pg);
                    float cn = fv * cc[p] + iv * gg;
                    cc[p] = cn;
                    float hv = ov * tanh_f(cn);
                    us hi, lo; bsplit(hv, hi, lo);
                    hstg[b * 8 + cu]        = hi;
                    hstg[1024 + b * 8 + cu] = lo;
                    if (layer == 1 && t == Tt - 1)
                        d_h1f[b * Hh + j] = hv;
                }
            }
            __syncthreads();

            // ---- coalesced h writeback (first 256 threads) ----
            if (tid < 256) {
                const int pl = tid >> 7, b = tid & 127;
                uint4 v = *(const uint4*)(hstg + pl * 1024 + b * 8);
                us* dst = (layer ? &d_h1[wr][pl][b][cta * 8]
                                 : &d_h0[wr][pl][b][cta * 8]);
                *(uint4*)dst = v;
            }

            if (layer == 0) {
                grid_barrier(t + 1);     // single barrier per step
                if (g_abort) break;
            } else {
                __syncthreads();         // protect hstg reuse within CTA
            }
        }
    }
}

// ---------------- fc head ----------------
__global__ void fc_kernel(const float* __restrict__ fcW,
                          const float* __restrict__ fcb,
                          float* __restrict__ out)
{
    __shared__ float red[256];
    int b = blockIdx.x, tid = threadIdx.x;
    float s = 0.f;
    for (int jj = tid; jj < Hh; jj += 256) s += d_h1f[b * Hh + jj] * fcW[jj];
    red[tid] = s;
    __syncthreads();
    for (int o = 128; o > 0; o >>= 1) {
        if (tid < o) red[tid] += red[tid + o];
        __syncthreads();
    }
    if (tid == 0) out[b] = red[0] + fcb[0];
}

// ---------------- launch (5 graph nodes) ----------------
extern "C" void kernel_launch(void* const* d_in, const int* in_sizes, int n_in,
                              void* d_out, int out_size)
{
    const float* x        = (const float*)d_in[0];
    const float* boundary = (const float*)d_in[1];
    const float* Wx0      = (const float*)d_in[2];
    const float* bx0      = (const float*)d_in[3];
    const float* Uh0      = (const float*)d_in[4];
    const float* bh0      = (const float*)d_in[5];
    const float* Wb0      = (const float*)d_in[6];
    const float* bb0      = (const float*)d_in[7];
    const float* Wx1      = (const float*)d_in[8];
    const float* bx1      = (const float*)d_in[9];
    const float* Uh1      = (const float*)d_in[10];
    const float* bh1      = (const float*)d_in[11];
    const float* Wb1      = (const float*)d_in[12];
    const float* bb1      = (const float*)d_in[13];
    const float* fcW      = (const float*)d_in[14];
    const float* fcb      = (const float*)d_in[15];
    float* out            = (float*)d_out;

    cudaFuncSetAttribute(lstm_mma, cudaFuncAttributeMaxDynamicSharedMemorySize, DYN_SMEM);

    setup_misc<<<(Bb * Hh) / 256, 256>>>(boundary, bx0, bh0, bb0, Wb0, bx1, bh1, bb1, Wb1);
    setup_x<<<(Tt * Bb * INP) / 256, 256>>>(x);
    repack_w<<<(128 * 49 * 32 * 64) / 256, 256>>>(Uh0, Wx0, Wx1, Uh1);
    lstm_mma<<<NBLK, NTHR, DYN_SMEM>>>();
    fc_kernel<<<Bb, 256>>>(fcW, fcb, out);
}